// round 1
// baseline (speedup 1.0000x reference)
#include <cuda_runtime.h>
#include <math.h>

// Problem constants
constexpr int Bb = 2;
constexpr int Ss = 2048;
constexpr int Dd = 768;
constexpr int Hh = 12;
constexpr int DHd = 64;
constexpr int WIN = 128;

// Scratch (device globals; no allocation allowed)
__device__ float g_Q[Bb * Ss * Hh * DHd];
__device__ float g_K[Bb * Ss * Hh * DHd];
__device__ float g_V[Bb * Ss * Hh * DHd];
__device__ float g_Z[Bb * Ss * Hh * DHd];

// ---------------------------------------------------------------------------
// Generic SGEMM: C[M,N] = A[M,K] * B[K,N] + bias[N]
// HEADB=true: B is (H, K, 64) head-blocked; with BN=64 tiles aligned to heads,
// each block sees a contiguous row-major K x 64 matrix.
// BM=128, BN=64, BK=16, 256 threads, 8x4 micro-tile.
// ---------------------------------------------------------------------------
template <bool HEADB>
__global__ __launch_bounds__(256) void sgemm_k(
    const float* __restrict__ A, const float* __restrict__ Bm,
    const float* __restrict__ bias, float* __restrict__ C,
    int M, int N, int K)
{
    __shared__ float As[16][132];  // transposed A tile, padded (row = k)
    __shared__ float Bs[16][64];

    const int t  = threadIdx.x;
    const int m0 = blockIdx.y * 128;
    const int n0 = blockIdx.x * 64;

    const float* bbase;
    int ldb;
    if (HEADB) { bbase = Bm + (size_t)(n0 >> 6) * K * 64; ldb = 64; }
    else       { bbase = Bm + n0;                          ldb = N;  }

    const int ty = t >> 4;   // 0..15 -> m rows ty*8..ty*8+7
    const int tx = t & 15;   // 0..15 -> n cols tx*4..tx*4+3

    float acc[8][4];
#pragma unroll
    for (int i = 0; i < 8; i++)
#pragma unroll
        for (int j = 0; j < 4; j++) acc[i][j] = 0.0f;

    for (int k0 = 0; k0 < K; k0 += 16) {
        // Load A tile (128x16), store transposed
#pragma unroll
        for (int i = 0; i < 2; i++) {
            int idx = t + i * 256;           // 0..511 float4s
            int r   = idx >> 2;              // 0..127
            int c4  = (idx & 3) * 4;         // 0,4,8,12
            float4 v = *(const float4*)&A[(size_t)(m0 + r) * K + k0 + c4];
            As[c4 + 0][r] = v.x;
            As[c4 + 1][r] = v.y;
            As[c4 + 2][r] = v.z;
            As[c4 + 3][r] = v.w;
        }
        // Load B tile (16x64)
        {
            int kk = t >> 4;                 // 0..15
            int n4 = (t & 15) * 4;           // 0..60
            float4 v = *(const float4*)&bbase[(size_t)(k0 + kk) * ldb + n4];
            *(float4*)&Bs[kk][n4] = v;
        }
        __syncthreads();

#pragma unroll
        for (int k = 0; k < 16; k++) {
            float4 a0 = *(float4*)&As[k][ty * 8];
            float4 a1 = *(float4*)&As[k][ty * 8 + 4];
            float4 b0 = *(float4*)&Bs[k][tx * 4];
            float a[8] = {a0.x, a0.y, a0.z, a0.w, a1.x, a1.y, a1.z, a1.w};
            float bb[4] = {b0.x, b0.y, b0.z, b0.w};
#pragma unroll
            for (int i = 0; i < 8; i++)
#pragma unroll
                for (int j = 0; j < 4; j++)
                    acc[i][j] = fmaf(a[i], bb[j], acc[i][j]);
        }
        __syncthreads();
    }

    float4 bv = *(const float4*)&bias[n0 + tx * 4];
#pragma unroll
    for (int i = 0; i < 8; i++) {
        float4 o;
        o.x = acc[i][0] + bv.x;
        o.y = acc[i][1] + bv.y;
        o.z = acc[i][2] + bv.z;
        o.w = acc[i][3] + bv.w;
        *(float4*)&C[(size_t)(m0 + ty * 8 + i) * N + n0 + tx * 4] = o;
    }
}

// ---------------------------------------------------------------------------
// Rotary (full head, ROT == DH == 64). Pair (i, i+32) shares angle pos/freq[i].
// ---------------------------------------------------------------------------
__global__ __launch_bounds__(256) void rotary_k(float* __restrict__ Q,
                                                float* __restrict__ K)
{
    const int total_half = Bb * Ss * Hh * 32;
    int tid = blockIdx.x * blockDim.x + threadIdx.x;
    if (tid >= 2 * total_half) return;

    float* buf = (tid < total_half) ? Q : K;
    int id  = (tid < total_half) ? tid : tid - total_half;
    int i   = id & 31;
    int bsh = id >> 5;
    int s   = (bsh / Hh) % Ss;

    // freq[i] = 10000^(2i/64); angle = pos / freq[i]
    float inv_freq = expf(-(float)(2 * i) * (1.0f / 64.0f) * 9.210340371976184f);
    float ang = (float)s * inv_freq;
    float sn, cs;
    sincosf(ang, &sn, &cs);

    size_t base = (size_t)bsh * 64;
    float x = buf[base + i];
    float y = buf[base + i + 32];
    buf[base + i]      = x * cs - y * sn;
    buf[base + i + 32] = y * cs + x * sn;
}

// ---------------------------------------------------------------------------
// Sliding-window attention. Block = (b, h, 64-query tile). Window = 128 keys
// -> key range for tile = [q0-128, q0+63] = 3 chunks of 64.
// Shared: Qs[64][65], KVs[64][65], Sc[64][192].
// ---------------------------------------------------------------------------
__global__ __launch_bounds__(256) void attn_k(
    const float* __restrict__ Q, const float* __restrict__ K,
    const float* __restrict__ V, float* __restrict__ Z)
{
    extern __shared__ float sm[];
    float* Qs  = sm;                 // 64*65
    float* KVs = sm + 64 * 65;       // 64*65
    float* Sc  = sm + 2 * 64 * 65;   // 64*192

    const int t  = threadIdx.x;
    const int q0 = blockIdx.x * 64;
    const int h  = blockIdx.y;
    const int b  = blockIdx.z;

    const int ty4 = (t >> 4) * 4;    // query rows ty4..ty4+3
    const int tx4 = (t & 15) * 4;    // key cols / d cols tx4..tx4+3

    // Load Q tile (64 rows x 64 dims)
#pragma unroll
    for (int i = 0; i < 4; i++) {
        int idx = t + i * 256;       // 0..1023 float4s
        int r = idx >> 4;            // 0..63
        int c = (idx & 15) * 4;
        float4 v = *(const float4*)&Q[(((size_t)(b * Ss + q0 + r)) * Hh + h) * 64 + c];
        Qs[r * 65 + c + 0] = v.x;
        Qs[r * 65 + c + 1] = v.y;
        Qs[r * 65 + c + 2] = v.z;
        Qs[r * 65 + c + 3] = v.w;
    }

    // ---- scores: 3 chunks of 64 keys ----
    for (int c = 0; c < 3; c++) {
        const int j0 = q0 - 128 + c * 64;
        __syncthreads();
        // load K chunk
#pragma unroll
        for (int i = 0; i < 4; i++) {
            int idx = t + i * 256;
            int r = idx >> 4;
            int cc = (idx & 15) * 4;
            int jg = j0 + r;
            float4 v = make_float4(0.f, 0.f, 0.f, 0.f);
            if (jg >= 0)
                v = *(const float4*)&K[(((size_t)(b * Ss + jg)) * Hh + h) * 64 + cc];
            KVs[r * 65 + cc + 0] = v.x;
            KVs[r * 65 + cc + 1] = v.y;
            KVs[r * 65 + cc + 2] = v.z;
            KVs[r * 65 + cc + 3] = v.w;
        }
        __syncthreads();

        float accs[4][4];
#pragma unroll
        for (int i = 0; i < 4; i++)
#pragma unroll
            for (int j = 0; j < 4; j++) accs[i][j] = 0.0f;

#pragma unroll 8
        for (int d = 0; d < 64; d++) {
            float a[4], bb[4];
#pragma unroll
            for (int i = 0; i < 4; i++) a[i]  = Qs[(ty4 + i) * 65 + d];
#pragma unroll
            for (int j = 0; j < 4; j++) bb[j] = KVs[(tx4 + j) * 65 + d];
#pragma unroll
            for (int i = 0; i < 4; i++)
#pragma unroll
                for (int j = 0; j < 4; j++)
                    accs[i][j] = fmaf(a[i], bb[j], accs[i][j]);
        }

        // mask + scale, write to score buffer
#pragma unroll
        for (int i = 0; i < 4; i++) {
            int qg = q0 + ty4 + i;
#pragma unroll
            for (int j = 0; j < 4; j++) {
                int jg = j0 + tx4 + j;
                bool ok = (jg >= 0) && (jg <= qg) && (jg > qg - WIN);
                Sc[(ty4 + i) * 192 + c * 64 + tx4 + j] =
                    ok ? accs[i][j] * 0.125f : -1e30f;
            }
        }
    }
    __syncthreads();

    // ---- softmax: 4 threads per row, 48 cols each ----
    {
        int r = t >> 2;
        int p = t & 3;
        float mx = -1e30f;
        for (int jj = p * 48; jj < p * 48 + 48; jj++)
            mx = fmaxf(mx, Sc[r * 192 + jj]);
        mx = fmaxf(mx, __shfl_xor_sync(0xFFFFFFFFu, mx, 1));
        mx = fmaxf(mx, __shfl_xor_sync(0xFFFFFFFFu, mx, 2));
        float sum = 0.0f;
        for (int jj = p * 48; jj < p * 48 + 48; jj++) {
            float e = __expf(Sc[r * 192 + jj] - mx);
            Sc[r * 192 + jj] = e;
            sum += e;
        }
        sum += __shfl_xor_sync(0xFFFFFFFFu, sum, 1);
        sum += __shfl_xor_sync(0xFFFFFFFFu, sum, 2);
        float inv = 1.0f / sum;
        for (int jj = p * 48; jj < p * 48 + 48; jj++)
            Sc[r * 192 + jj] *= inv;
    }

    // ---- P @ V ----
    float o[4][4];
#pragma unroll
    for (int i = 0; i < 4; i++)
#pragma unroll
        for (int j = 0; j < 4; j++) o[i][j] = 0.0f;

    for (int c = 0; c < 3; c++) {
        const int j0 = q0 - 128 + c * 64;
        __syncthreads();
#pragma unroll
        for (int i = 0; i < 4; i++) {
            int idx = t + i * 256;
            int r = idx >> 4;
            int cc = (idx & 15) * 4;
            int jg = j0 + r;
            float4 v = make_float4(0.f, 0.f, 0.f, 0.f);
            if (jg >= 0)
                v = *(const float4*)&V[(((size_t)(b * Ss + jg)) * Hh + h) * 64 + cc];
            KVs[r * 65 + cc + 0] = v.x;
            KVs[r * 65 + cc + 1] = v.y;
            KVs[r * 65 + cc + 2] = v.z;
            KVs[r * 65 + cc + 3] = v.w;
        }
        __syncthreads();

#pragma unroll 8
        for (int jj = 0; jj < 64; jj++) {
            float p4[4], vv[4];
#pragma unroll
            for (int i = 0; i < 4; i++) p4[i] = Sc[(ty4 + i) * 192 + c * 64 + jj];
#pragma unroll
            for (int j = 0; j < 4; j++) vv[j] = KVs[jj * 65 + tx4 + j];
#pragma unroll
            for (int i = 0; i < 4; i++)
#pragma unroll
                for (int j = 0; j < 4; j++)
                    o[i][j] = fmaf(p4[i], vv[j], o[i][j]);
        }
    }

    // write Z[b][q][h][d]
#pragma unroll
    for (int i = 0; i < 4; i++)
#pragma unroll
        for (int j = 0; j < 4; j++)
            Z[(((size_t)(b * Ss + q0 + ty4 + i)) * Hh + h) * 64 + tx4 + j] = o[i][j];
}

// ---------------------------------------------------------------------------
extern "C" void kernel_launch(void* const* d_in, const int* in_sizes, int n_in,
                              void* d_out, int out_size)
{
    const float* qin = (const float*)d_in[0];
    const float* kin = (const float*)d_in[1];
    const float* vin = (const float*)d_in[2];
    const float* WQ  = (const float*)d_in[3];
    const float* WK  = (const float*)d_in[4];
    const float* WV  = (const float*)d_in[5];
    const float* WO  = (const float*)d_in[6];
    const float* bQ  = (const float*)d_in[7];
    const float* bK  = (const float*)d_in[8];
    const float* bV  = (const float*)d_in[9];
    const float* bO  = (const float*)d_in[10];
    float* out = (float*)d_out;

    float *pQ, *pK, *pV, *pZ;
    cudaGetSymbolAddress((void**)&pQ, g_Q);
    cudaGetSymbolAddress((void**)&pK, g_K);
    cudaGetSymbolAddress((void**)&pV, g_V);
    cudaGetSymbolAddress((void**)&pZ, g_Z);

    const int M = Bb * Ss;       // 4096
    const int N = Hh * DHd;      // 768
    const int Kd = Dd;           // 768
    dim3 gg(N / 64, M / 128);

    sgemm_k<true><<<gg, 256>>>(qin, WQ, bQ, pQ, M, N, Kd);
    sgemm_k<true><<<gg, 256>>>(kin, WK, bK, pK, M, N, Kd);
    sgemm_k<true><<<gg, 256>>>(vin, WV, bV, pV, M, N, Kd);

    int rot_threads = 2 * Bb * Ss * Hh * 32;
    rotary_k<<<rot_threads / 256, 256>>>(pQ, pK);

    size_t smem = (size_t)(2 * 64 * 65 + 64 * 192) * sizeof(float);  // 82432 B
    cudaFuncSetAttribute(attn_k, cudaFuncAttributeMaxDynamicSharedMemorySize,
                         (int)smem);
    attn_k<<<dim3(Ss / 64, Hh, Bb), 256, smem>>>(pQ, pK, pV, pZ);

    sgemm_k<false><<<gg, 256>>>(pZ, WO, bO, out, M, N, Kd);
}

// round 2
// speedup vs baseline: 1.9742x; 1.9742x over previous
#include <cuda_runtime.h>
#include <math.h>
#include <stdint.h>

// Problem constants
constexpr int Bb = 2;
constexpr int Ss = 2048;
constexpr int Dd = 768;
constexpr int Hh = 12;
constexpr int DHd = 64;
constexpr int WIN = 128;

// Scratch (device globals; no allocation allowed)
__device__ float g_Q[Bb * Ss * Hh * DHd];
__device__ float g_K[Bb * Ss * Hh * DHd];
__device__ float g_V[Bb * Ss * Hh * DHd];
__device__ float g_Z[Bb * Ss * Hh * DHd];

__device__ __forceinline__ uint32_t f2tf32(float x) {
    uint32_t u;
    asm("cvt.rna.tf32.f32 %0, %1;" : "=r"(u) : "f"(x));
    return u;
}

// ---------------------------------------------------------------------------
// tf32 tensor-core GEMM: C[M,N] = A[M,K] * B[K,N] + bias[N]
// BM=128, BN=64, BK=32. 256 threads = 8 warps (4x2), warp tile 32x32.
// mma.sync.aligned.m16n8k8.row.col.f32.tf32.tf32.f32
// Shared pads chosen so fragment loads are bank-conflict free:
//   As[128][36]: frag bank = (4*row + k) % 32 -> all distinct
//   Bs[32][72] : frag bank = (8*tig + group) % 32 -> all distinct
// HEADB=true: B is (H, K, 64) head-blocked; BN=64 aligned to heads.
// ---------------------------------------------------------------------------
template <bool HEADB>
__global__ __launch_bounds__(256) void tgemm_k(
    const float* __restrict__ A, const float* __restrict__ Bm,
    const float* __restrict__ bias, float* __restrict__ C,
    int M, int N, int K)
{
    __shared__ uint32_t As[128][36];
    __shared__ uint32_t Bs[32][72];

    const int t  = threadIdx.x;
    const int m0 = blockIdx.y * 128;
    const int n0 = blockIdx.x * 64;

    const float* bbase;
    int ldb;
    if (HEADB) { bbase = Bm + (size_t)(n0 >> 6) * K * 64; ldb = 64; }
    else       { bbase = Bm + n0;                          ldb = N;  }

    const int warp  = t >> 5;
    const int lane  = t & 31;
    const int wm    = (warp >> 1) * 32;   // warp m-offset (4 warps in m)
    const int wn    = (warp & 1) * 32;    // warp n-offset (2 warps in n)
    const int group = lane >> 2;          // 0..7
    const int tig   = lane & 3;           // 0..3

    float acc[2][4][4];
#pragma unroll
    for (int mt = 0; mt < 2; mt++)
#pragma unroll
        for (int nt = 0; nt < 4; nt++)
#pragma unroll
            for (int j = 0; j < 4; j++) acc[mt][nt][j] = 0.0f;

    for (int k0 = 0; k0 < K; k0 += 32) {
        // Load A tile 128x32 (4 float4 per thread), convert to tf32
#pragma unroll
        for (int i = 0; i < 4; i++) {
            int idx = t + i * 256;        // 0..1023
            int r   = idx >> 3;           // 0..127
            int c4  = (idx & 7) * 4;      // 0..28
            float4 v = *(const float4*)&A[(size_t)(m0 + r) * K + k0 + c4];
            uint4 u;
            u.x = f2tf32(v.x); u.y = f2tf32(v.y);
            u.z = f2tf32(v.z); u.w = f2tf32(v.w);
            *(uint4*)&As[r][c4] = u;
        }
        // Load B tile 32x64 (2 float4 per thread)
#pragma unroll
        for (int i = 0; i < 2; i++) {
            int idx = t + i * 256;        // 0..511
            int r   = idx >> 4;           // 0..31
            int c4  = (idx & 15) * 4;     // 0..60
            float4 v = *(const float4*)&bbase[(size_t)(k0 + r) * ldb + c4];
            uint4 u;
            u.x = f2tf32(v.x); u.y = f2tf32(v.y);
            u.z = f2tf32(v.z); u.w = f2tf32(v.w);
            *(uint4*)&Bs[r][c4] = u;
        }
        __syncthreads();

#pragma unroll
        for (int kk = 0; kk < 4; kk++) {
            const int k8 = kk * 8;
            uint32_t a[2][4], b[4][2];
#pragma unroll
            for (int mt = 0; mt < 2; mt++) {
                int row = wm + mt * 16 + group;
                a[mt][0] = As[row][k8 + tig];
                a[mt][1] = As[row + 8][k8 + tig];
                a[mt][2] = As[row][k8 + tig + 4];
                a[mt][3] = As[row + 8][k8 + tig + 4];
            }
#pragma unroll
            for (int nt = 0; nt < 4; nt++) {
                int col = wn + nt * 8 + group;
                b[nt][0] = Bs[k8 + tig][col];
                b[nt][1] = Bs[k8 + tig + 4][col];
            }
#pragma unroll
            for (int mt = 0; mt < 2; mt++)
#pragma unroll
                for (int nt = 0; nt < 4; nt++) {
                    asm volatile(
                        "mma.sync.aligned.m16n8k8.row.col.f32.tf32.tf32.f32 "
                        "{%0,%1,%2,%3}, {%4,%5,%6,%7}, {%8,%9}, {%0,%1,%2,%3};\n"
                        : "+f"(acc[mt][nt][0]), "+f"(acc[mt][nt][1]),
                          "+f"(acc[mt][nt][2]), "+f"(acc[mt][nt][3])
                        : "r"(a[mt][0]), "r"(a[mt][1]), "r"(a[mt][2]), "r"(a[mt][3]),
                          "r"(b[nt][0]), "r"(b[nt][1]));
                }
        }
        __syncthreads();
    }

    // Epilogue: bias + store. c0,c1 -> (row=group, col=tig*2,+1); c2,c3 -> row=group+8
#pragma unroll
    for (int mt = 0; mt < 2; mt++) {
#pragma unroll
        for (int nt = 0; nt < 4; nt++) {
            int col  = n0 + wn + nt * 8 + tig * 2;
            float bx = bias[col];
            float by = bias[col + 1];
            int r0 = m0 + wm + mt * 16 + group;
            float2 o0 = make_float2(acc[mt][nt][0] + bx, acc[mt][nt][1] + by);
            float2 o1 = make_float2(acc[mt][nt][2] + bx, acc[mt][nt][3] + by);
            *(float2*)&C[(size_t)r0 * N + col]       = o0;
            *(float2*)&C[(size_t)(r0 + 8) * N + col] = o1;
        }
    }
}

// ---------------------------------------------------------------------------
// Rotary (full head, ROT == DH == 64). Pair (i, i+32) shares angle pos/freq[i].
// ---------------------------------------------------------------------------
__global__ __launch_bounds__(256) void rotary_k(float* __restrict__ Q,
                                                float* __restrict__ K)
{
    const int total_half = Bb * Ss * Hh * 32;
    int tid = blockIdx.x * blockDim.x + threadIdx.x;
    if (tid >= 2 * total_half) return;

    float* buf = (tid < total_half) ? Q : K;
    int id  = (tid < total_half) ? tid : tid - total_half;
    int i   = id & 31;
    int bsh = id >> 5;
    int s   = (bsh / Hh) % Ss;

    float inv_freq = expf(-(float)(2 * i) * (1.0f / 64.0f) * 9.210340371976184f);
    float ang = (float)s * inv_freq;
    float sn, cs;
    sincosf(ang, &sn, &cs);

    size_t base = (size_t)bsh * 64;
    float x = buf[base + i];
    float y = buf[base + i + 32];
    buf[base + i]      = x * cs - y * sn;
    buf[base + i + 32] = y * cs + x * sn;
}

// ---------------------------------------------------------------------------
// Sliding-window attention. Block = (b, h, 64-query tile). Window = 128 keys
// -> key range for tile = [q0-128, q0+63] = 3 chunks of 64.
// ---------------------------------------------------------------------------
__global__ __launch_bounds__(256) void attn_k(
    const float* __restrict__ Q, const float* __restrict__ K,
    const float* __restrict__ V, float* __restrict__ Z)
{
    extern __shared__ float sm[];
    float* Qs  = sm;                 // 64*65
    float* KVs = sm + 64 * 65;       // 64*65
    float* Sc  = sm + 2 * 64 * 65;   // 64*192

    const int t  = threadIdx.x;
    const int q0 = blockIdx.x * 64;
    const int h  = blockIdx.y;
    const int b  = blockIdx.z;

    const int ty4 = (t >> 4) * 4;
    const int tx4 = (t & 15) * 4;

#pragma unroll
    for (int i = 0; i < 4; i++) {
        int idx = t + i * 256;
        int r = idx >> 4;
        int c = (idx & 15) * 4;
        float4 v = *(const float4*)&Q[(((size_t)(b * Ss + q0 + r)) * Hh + h) * 64 + c];
        Qs[r * 65 + c + 0] = v.x;
        Qs[r * 65 + c + 1] = v.y;
        Qs[r * 65 + c + 2] = v.z;
        Qs[r * 65 + c + 3] = v.w;
    }

    for (int c = 0; c < 3; c++) {
        const int j0 = q0 - 128 + c * 64;
        __syncthreads();
#pragma unroll
        for (int i = 0; i < 4; i++) {
            int idx = t + i * 256;
            int r = idx >> 4;
            int cc = (idx & 15) * 4;
            int jg = j0 + r;
            float4 v = make_float4(0.f, 0.f, 0.f, 0.f);
            if (jg >= 0)
                v = *(const float4*)&K[(((size_t)(b * Ss + jg)) * Hh + h) * 64 + cc];
            KVs[r * 65 + cc + 0] = v.x;
            KVs[r * 65 + cc + 1] = v.y;
            KVs[r * 65 + cc + 2] = v.z;
            KVs[r * 65 + cc + 3] = v.w;
        }
        __syncthreads();

        float accs[4][4];
#pragma unroll
        for (int i = 0; i < 4; i++)
#pragma unroll
            for (int j = 0; j < 4; j++) accs[i][j] = 0.0f;

#pragma unroll 8
        for (int d = 0; d < 64; d++) {
            float a[4], bb[4];
#pragma unroll
            for (int i = 0; i < 4; i++) a[i]  = Qs[(ty4 + i) * 65 + d];
#pragma unroll
            for (int j = 0; j < 4; j++) bb[j] = KVs[(tx4 + j) * 65 + d];
#pragma unroll
            for (int i = 0; i < 4; i++)
#pragma unroll
                for (int j = 0; j < 4; j++)
                    accs[i][j] = fmaf(a[i], bb[j], accs[i][j]);
        }

#pragma unroll
        for (int i = 0; i < 4; i++) {
            int qg = q0 + ty4 + i;
#pragma unroll
            for (int j = 0; j < 4; j++) {
                int jg = j0 + tx4 + j;
                bool ok = (jg >= 0) && (jg <= qg) && (jg > qg - WIN);
                Sc[(ty4 + i) * 192 + c * 64 + tx4 + j] =
                    ok ? accs[i][j] * 0.125f : -1e30f;
            }
        }
    }
    __syncthreads();

    {
        int r = t >> 2;
        int p = t & 3;
        float mx = -1e30f;
        for (int jj = p * 48; jj < p * 48 + 48; jj++)
            mx = fmaxf(mx, Sc[r * 192 + jj]);
        mx = fmaxf(mx, __shfl_xor_sync(0xFFFFFFFFu, mx, 1));
        mx = fmaxf(mx, __shfl_xor_sync(0xFFFFFFFFu, mx, 2));
        float sum = 0.0f;
        for (int jj = p * 48; jj < p * 48 + 48; jj++) {
            float e = __expf(Sc[r * 192 + jj] - mx);
            Sc[r * 192 + jj] = e;
            sum += e;
        }
        sum += __shfl_xor_sync(0xFFFFFFFFu, sum, 1);
        sum += __shfl_xor_sync(0xFFFFFFFFu, sum, 2);
        float inv = 1.0f / sum;
        for (int jj = p * 48; jj < p * 48 + 48; jj++)
            Sc[r * 192 + jj] *= inv;
    }

    float o[4][4];
#pragma unroll
    for (int i = 0; i < 4; i++)
#pragma unroll
        for (int j = 0; j < 4; j++) o[i][j] = 0.0f;

    for (int c = 0; c < 3; c++) {
        const int j0 = q0 - 128 + c * 64;
        __syncthreads();
#pragma unroll
        for (int i = 0; i < 4; i++) {
            int idx = t + i * 256;
            int r = idx >> 4;
            int cc = (idx & 15) * 4;
            int jg = j0 + r;
            float4 v = make_float4(0.f, 0.f, 0.f, 0.f);
            if (jg >= 0)
                v = *(const float4*)&V[(((size_t)(b * Ss + jg)) * Hh + h) * 64 + cc];
            KVs[r * 65 + cc + 0] = v.x;
            KVs[r * 65 + cc + 1] = v.y;
            KVs[r * 65 + cc + 2] = v.z;
            KVs[r * 65 + cc + 3] = v.w;
        }
        __syncthreads();

#pragma unroll 8
        for (int jj = 0; jj < 64; jj++) {
            float p4[4], vv[4];
#pragma unroll
            for (int i = 0; i < 4; i++) p4[i] = Sc[(ty4 + i) * 192 + c * 64 + jj];
#pragma unroll
            for (int j = 0; j < 4; j++) vv[j] = KVs[jj * 65 + tx4 + j];
#pragma unroll
            for (int i = 0; i < 4; i++)
#pragma unroll
                for (int j = 0; j < 4; j++)
                    o[i][j] = fmaf(p4[i], vv[j], o[i][j]);
        }
    }

#pragma unroll
    for (int i = 0; i < 4; i++)
#pragma unroll
        for (int j = 0; j < 4; j++)
            Z[(((size_t)(b * Ss + q0 + ty4 + i)) * Hh + h) * 64 + tx4 + j] = o[i][j];
}

// ---------------------------------------------------------------------------
extern "C" void kernel_launch(void* const* d_in, const int* in_sizes, int n_in,
                              void* d_out, int out_size)
{
    const float* qin = (const float*)d_in[0];
    const float* kin = (const float*)d_in[1];
    const float* vin = (const float*)d_in[2];
    const float* WQ  = (const float*)d_in[3];
    const float* WK  = (const float*)d_in[4];
    const float* WV  = (const float*)d_in[5];
    const float* WO  = (const float*)d_in[6];
    const float* bQ  = (const float*)d_in[7];
    const float* bK  = (const float*)d_in[8];
    const float* bV  = (const float*)d_in[9];
    const float* bO  = (const float*)d_in[10];
    float* out = (float*)d_out;

    float *pQ, *pK, *pV, *pZ;
    cudaGetSymbolAddress((void**)&pQ, g_Q);
    cudaGetSymbolAddress((void**)&pK, g_K);
    cudaGetSymbolAddress((void**)&pV, g_V);
    cudaGetSymbolAddress((void**)&pZ, g_Z);

    const int M = Bb * Ss;       // 4096
    const int N = Hh * DHd;      // 768
    const int Kd = Dd;           // 768
    dim3 gg(N / 64, M / 128);

    tgemm_k<true><<<gg, 256>>>(qin, WQ, bQ, pQ, M, N, Kd);
    tgemm_k<true><<<gg, 256>>>(kin, WK, bK, pK, M, N, Kd);
    tgemm_k<true><<<gg, 256>>>(vin, WV, bV, pV, M, N, Kd);

    int rot_threads = 2 * Bb * Ss * Hh * 32;
    rotary_k<<<rot_threads / 256, 256>>>(pQ, pK);

    size_t smem = (size_t)(2 * 64 * 65 + 64 * 192) * sizeof(float);  // 82432 B
    cudaFuncSetAttribute(attn_k, cudaFuncAttributeMaxDynamicSharedMemorySize,
                         (int)smem);
    attn_k<<<dim3(Ss / 64, Hh, Bb), 256, smem>>>(pQ, pK, pV, pZ);

    tgemm_k<false><<<gg, 256>>>(pZ, WO, bO, out, M, N, Kd);
}

// round 3
// speedup vs baseline: 2.1953x; 1.1120x over previous
#include <cuda_runtime.h>
#include <math.h>
#include <stdint.h>

// Problem constants
constexpr int Bb = 2;
constexpr int Ss = 2048;
constexpr int Dd = 768;
constexpr int Hh = 12;
constexpr int DHd = 64;
constexpr int WIN = 128;

// Scratch (device globals; no allocation allowed)
__device__ float g_Q[Bb * Ss * Hh * DHd];
__device__ float g_K[Bb * Ss * Hh * DHd];
__device__ float g_V[Bb * Ss * Hh * DHd];
__device__ float g_Z[Bb * Ss * Hh * DHd];

using ull = unsigned long long;

__device__ __forceinline__ uint32_t f2tf32(float x) {
    uint32_t u;
    asm("cvt.rna.tf32.f32 %0, %1;" : "=r"(u) : "f"(x));
    return u;
}
__device__ __forceinline__ ull pack2(float x, float y) {
    ull r;
    asm("mov.b64 %0, {%1, %2};" : "=l"(r) : "f"(x), "f"(y));
    return r;
}
__device__ __forceinline__ void unpack2(ull v, float& x, float& y) {
    asm("mov.b64 {%0, %1}, %2;" : "=f"(x), "=f"(y) : "l"(v));
}
__device__ __forceinline__ void ffma2(ull& d, ull a, ull b) {
    asm("fma.rn.f32x2 %0, %1, %2, %0;" : "+l"(d) : "l"(a), "l"(b));
}

// ---------------------------------------------------------------------------
// tf32 tensor-core GEMM with register double-buffering.
// C[M,N] = A[M,K]*B[K,N] + bias[N].  BM=128, BN=64, BK=32, 256 thr, 8 warps.
// blockIdx.z selects one of up to 3 (A,B,bias,C) problem instances (QKV fused).
// ---------------------------------------------------------------------------
template <bool HEADB>
__global__ __launch_bounds__(256, 2) void tgemm_k(
    const float* __restrict__ A0, const float* __restrict__ A1, const float* __restrict__ A2,
    const float* __restrict__ Bm0, const float* __restrict__ Bm1, const float* __restrict__ Bm2,
    const float* __restrict__ bias0, const float* __restrict__ bias1, const float* __restrict__ bias2,
    float* __restrict__ C0, float* __restrict__ C1, float* __restrict__ C2,
    int M, int N, int K)
{
    __shared__ uint32_t As[128][36];
    __shared__ uint32_t Bs[32][72];

    const int z = blockIdx.z;
    const float* A    = (z == 0) ? A0    : (z == 1) ? A1    : A2;
    const float* Bm   = (z == 0) ? Bm0   : (z == 1) ? Bm1   : Bm2;
    const float* bias = (z == 0) ? bias0 : (z == 1) ? bias1 : bias2;
    float*       C    = (z == 0) ? C0    : (z == 1) ? C1    : C2;

    const int t  = threadIdx.x;
    const int m0 = blockIdx.y * 128;
    const int n0 = blockIdx.x * 64;

    const float* bbase;
    int ldb;
    if (HEADB) { bbase = Bm + (size_t)(n0 >> 6) * K * 64; ldb = 64; }
    else       { bbase = Bm + n0;                          ldb = N;  }

    const int warp  = t >> 5;
    const int lane  = t & 31;
    const int wm    = (warp >> 1) * 32;
    const int wn    = (warp & 1) * 32;
    const int group = lane >> 2;
    const int tig   = lane & 3;

    // addressing for tile loads
    const int ar  = t >> 3;          // 0..31 base row step pattern (idx>>3 with idx=t+i*256)
    const int ac4 = (t & 7) * 4;
    const int br  = t >> 4;
    const int bc4 = (t & 15) * 4;

    float4 ra[4];
    float4 rb[2];

    auto ldg = [&](int k0) {
#pragma unroll
        for (int i = 0; i < 4; i++) {
            int r = ar + i * 32;
            ra[i] = *(const float4*)&A[(size_t)(m0 + r) * K + k0 + ac4];
        }
#pragma unroll
        for (int i = 0; i < 2; i++) {
            int r = br + i * 16;
            rb[i] = *(const float4*)&bbase[(size_t)(k0 + r) * ldb + bc4];
        }
    };
    auto sts = [&]() {
#pragma unroll
        for (int i = 0; i < 4; i++) {
            int r = ar + i * 32;
            uint4 u;
            u.x = f2tf32(ra[i].x); u.y = f2tf32(ra[i].y);
            u.z = f2tf32(ra[i].z); u.w = f2tf32(ra[i].w);
            *(uint4*)&As[r][ac4] = u;
        }
#pragma unroll
        for (int i = 0; i < 2; i++) {
            int r = br + i * 16;
            uint4 u;
            u.x = f2tf32(rb[i].x); u.y = f2tf32(rb[i].y);
            u.z = f2tf32(rb[i].z); u.w = f2tf32(rb[i].w);
            *(uint4*)&Bs[r][bc4] = u;
        }
    };

    float acc[2][4][4];
#pragma unroll
    for (int mt = 0; mt < 2; mt++)
#pragma unroll
        for (int nt = 0; nt < 4; nt++)
#pragma unroll
            for (int j = 0; j < 4; j++) acc[mt][nt][j] = 0.0f;

    ldg(0);
    sts();
    __syncthreads();

    for (int k0 = 0; k0 < K; k0 += 32) {
        const bool notlast = (k0 + 32 < K);
        if (notlast) ldg(k0 + 32);   // prefetch next tile into registers

#pragma unroll
        for (int kk = 0; kk < 4; kk++) {
            const int k8 = kk * 8;
            uint32_t a[2][4], b[4][2];
#pragma unroll
            for (int mt = 0; mt < 2; mt++) {
                int row = wm + mt * 16 + group;
                a[mt][0] = As[row][k8 + tig];
                a[mt][1] = As[row + 8][k8 + tig];
                a[mt][2] = As[row][k8 + tig + 4];
                a[mt][3] = As[row + 8][k8 + tig + 4];
            }
#pragma unroll
            for (int nt = 0; nt < 4; nt++) {
                int col = wn + nt * 8 + group;
                b[nt][0] = Bs[k8 + tig][col];
                b[nt][1] = Bs[k8 + tig + 4][col];
            }
#pragma unroll
            for (int mt = 0; mt < 2; mt++)
#pragma unroll
                for (int nt = 0; nt < 4; nt++) {
                    asm volatile(
                        "mma.sync.aligned.m16n8k8.row.col.f32.tf32.tf32.f32 "
                        "{%0,%1,%2,%3}, {%4,%5,%6,%7}, {%8,%9}, {%0,%1,%2,%3};\n"
                        : "+f"(acc[mt][nt][0]), "+f"(acc[mt][nt][1]),
                          "+f"(acc[mt][nt][2]), "+f"(acc[mt][nt][3])
                        : "r"(a[mt][0]), "r"(a[mt][1]), "r"(a[mt][2]), "r"(a[mt][3]),
                          "r"(b[nt][0]), "r"(b[nt][1]));
                }
        }
        __syncthreads();
        if (notlast) {
            sts();
            __syncthreads();
        }
    }

#pragma unroll
    for (int mt = 0; mt < 2; mt++) {
#pragma unroll
        for (int nt = 0; nt < 4; nt++) {
            int col  = n0 + wn + nt * 8 + tig * 2;
            float bx = bias[col];
            float by = bias[col + 1];
            int r0 = m0 + wm + mt * 16 + group;
            float2 o0 = make_float2(acc[mt][nt][0] + bx, acc[mt][nt][1] + by);
            float2 o1 = make_float2(acc[mt][nt][2] + bx, acc[mt][nt][3] + by);
            *(float2*)&C[(size_t)r0 * N + col]       = o0;
            *(float2*)&C[(size_t)(r0 + 8) * N + col] = o1;
        }
    }
}

// ---------------------------------------------------------------------------
// Rotary (full head, ROT == DH == 64). Pair (i, i+32) shares angle pos/freq[i].
// ---------------------------------------------------------------------------
__global__ __launch_bounds__(256) void rotary_k(float* __restrict__ Q,
                                                float* __restrict__ K)
{
    const int total_half = Bb * Ss * Hh * 32;
    int tid = blockIdx.x * blockDim.x + threadIdx.x;
    if (tid >= 2 * total_half) return;

    float* buf = (tid < total_half) ? Q : K;
    int id  = (tid < total_half) ? tid : tid - total_half;
    int i   = id & 31;
    int bsh = id >> 5;
    int s   = (bsh / Hh) % Ss;

    float inv_freq = expf(-(float)(2 * i) * (1.0f / 64.0f) * 9.210340371976184f);
    float ang = (float)s * inv_freq;
    float sn, cs;
    sincosf(ang, &sn, &cs);

    size_t base = (size_t)bsh * 64;
    float x = buf[base + i];
    float y = buf[base + i + 32];
    buf[base + i]      = x * cs - y * sn;
    buf[base + i + 32] = y * cs + x * sn;
}

// ---------------------------------------------------------------------------
// Sliding-window attention with packed f32x2 FFMA.
// Block = (64-query tile, h, b). Keys: [q0-128, q0+63] = 3 chunks of 64.
// Qs[64][65] (q-major), K chunks in KVs[key][65], V chunks in KVs[key][68],
// Sc[64][196].
// ---------------------------------------------------------------------------
constexpr int QP  = 65;   // Qs pad
constexpr int KP  = 65;   // K chunk pad (score phase)
constexpr int VP  = 68;   // V chunk pad (PV phase, 16B-aligned rows)
constexpr int SCP = 196;  // score buffer pad (196 % 32 = 4 -> no softmax conflicts)

__global__ __launch_bounds__(256) void attn_k(
    const float* __restrict__ Q, const float* __restrict__ K,
    const float* __restrict__ V, float* __restrict__ Z)
{
    extern __shared__ float sm[];
    float* Qs  = sm;                       // 64*65   = 4160
    float* KVs = sm + 64 * QP;             // 64*68   = 4352 (max of KP/VP use)
    float* Sc  = sm + 64 * QP + 64 * VP;   // 64*196  = 12544

    const int t  = threadIdx.x;
    const int q0 = blockIdx.x * 64;
    const int h  = blockIdx.y;
    const int b  = blockIdx.z;

    const int ty4 = (t >> 4) * 4;
    const int tx4 = (t & 15) * 4;

    // Load Q tile (64 q x 64 d)
#pragma unroll
    for (int i = 0; i < 4; i++) {
        int idx = t + i * 256;
        int r = idx >> 4;
        int c = (idx & 15) * 4;
        float4 v = *(const float4*)&Q[(((size_t)(b * Ss + q0 + r)) * Hh + h) * 64 + c];
        Qs[r * QP + c + 0] = v.x;
        Qs[r * QP + c + 1] = v.y;
        Qs[r * QP + c + 2] = v.z;
        Qs[r * QP + c + 3] = v.w;
    }

    // ---- scores ----
    for (int c = 0; c < 3; c++) {
        const int j0 = q0 - 128 + c * 64;
        __syncthreads();
#pragma unroll
        for (int i = 0; i < 4; i++) {
            int idx = t + i * 256;
            int r = idx >> 4;
            int cc = (idx & 15) * 4;
            int jg = j0 + r;
            float4 v = make_float4(0.f, 0.f, 0.f, 0.f);
            if (jg >= 0)
                v = *(const float4*)&K[(((size_t)(b * Ss + jg)) * Hh + h) * 64 + cc];
            KVs[r * KP + cc + 0] = v.x;
            KVs[r * KP + cc + 1] = v.y;
            KVs[r * KP + cc + 2] = v.z;
            KVs[r * KP + cc + 3] = v.w;
        }
        __syncthreads();

        ull accp[4][2];   // [query i][key-pair jp]; pair = keys (2*jp, 2*jp+1)
#pragma unroll
        for (int i = 0; i < 4; i++) { accp[i][0] = 0ull; accp[i][1] = 0ull; }

#pragma unroll 4
        for (int d = 0; d < 64; d++) {
            float k0v = KVs[(tx4 + 0) * KP + d];
            float k1v = KVs[(tx4 + 1) * KP + d];
            float k2v = KVs[(tx4 + 2) * KP + d];
            float k3v = KVs[(tx4 + 3) * KP + d];
            ull kb0 = pack2(k0v, k1v);
            ull kb1 = pack2(k2v, k3v);
#pragma unroll
            for (int i = 0; i < 4; i++) {
                float av = Qs[(ty4 + i) * QP + d];
                ull ab = pack2(av, av);
                ffma2(accp[i][0], ab, kb0);
                ffma2(accp[i][1], ab, kb1);
            }
        }

#pragma unroll
        for (int i = 0; i < 4; i++) {
            float s0, s1, s2, s3;
            unpack2(accp[i][0], s0, s1);
            unpack2(accp[i][1], s2, s3);
            float sv[4] = {s0, s1, s2, s3};
            int qg = q0 + ty4 + i;
#pragma unroll
            for (int j = 0; j < 4; j++) {
                int jg = j0 + tx4 + j;
                bool ok = (jg >= 0) && (jg <= qg) && (jg > qg - WIN);
                Sc[(ty4 + i) * SCP + c * 64 + tx4 + j] = ok ? sv[j] * 0.125f : -1e30f;
            }
        }
    }
    __syncthreads();

    // ---- softmax: 4 threads per row, 48 cols each ----
    {
        int r = t >> 2;
        int p = t & 3;
        float mx = -1e30f;
        for (int jj = p * 48; jj < p * 48 + 48; jj++)
            mx = fmaxf(mx, Sc[r * SCP + jj]);
        mx = fmaxf(mx, __shfl_xor_sync(0xFFFFFFFFu, mx, 1));
        mx = fmaxf(mx, __shfl_xor_sync(0xFFFFFFFFu, mx, 2));
        float sum = 0.0f;
        for (int jj = p * 48; jj < p * 48 + 48; jj++) {
            float e = __expf(Sc[r * SCP + jj] - mx);
            Sc[r * SCP + jj] = e;
            sum += e;
        }
        sum += __shfl_xor_sync(0xFFFFFFFFu, sum, 1);
        sum += __shfl_xor_sync(0xFFFFFFFFu, sum, 2);
        float inv = 1.0f / sum;
        for (int jj = p * 48; jj < p * 48 + 48; jj++)
            Sc[r * SCP + jj] *= inv;
    }

    // ---- P @ V ----
    ull op[4][2];   // [query i][d-pair]; pair = dims (tx4+2*jp, tx4+2*jp+1)
#pragma unroll
    for (int i = 0; i < 4; i++) { op[i][0] = 0ull; op[i][1] = 0ull; }

    for (int c = 0; c < 3; c++) {
        const int j0 = q0 - 128 + c * 64;
        __syncthreads();
#pragma unroll
        for (int i = 0; i < 4; i++) {
            int idx = t + i * 256;
            int r = idx >> 4;
            int cc = (idx & 15) * 4;
            int jg = j0 + r;
            float4 v = make_float4(0.f, 0.f, 0.f, 0.f);
            if (jg >= 0)
                v = *(const float4*)&V[(((size_t)(b * Ss + jg)) * Hh + h) * 64 + cc];
            *(float4*)&KVs[r * VP + cc] = v;    // 16B-aligned row
        }
        __syncthreads();

#pragma unroll 4
        for (int jj = 0; jj < 64; jj++) {
            ulonglong2 vb = *(const ulonglong2*)&KVs[jj * VP + tx4];
#pragma unroll
            for (int i = 0; i < 4; i++) {
                float pv = Sc[(ty4 + i) * SCP + c * 64 + jj];
                ull pb = pack2(pv, pv);
                ffma2(op[i][0], pb, vb.x);
                ffma2(op[i][1], pb, vb.y);
            }
        }
    }

    // write Z[b][q][h][d]
#pragma unroll
    for (int i = 0; i < 4; i++) {
        float4 o;
        unpack2(op[i][0], o.x, o.y);
        unpack2(op[i][1], o.z, o.w);
        *(float4*)&Z[(((size_t)(b * Ss + q0 + ty4 + i)) * Hh + h) * 64 + tx4] = o;
    }
}

// ---------------------------------------------------------------------------
extern "C" void kernel_launch(void* const* d_in, const int* in_sizes, int n_in,
                              void* d_out, int out_size)
{
    const float* qin = (const float*)d_in[0];
    const float* kin = (const float*)d_in[1];
    const float* vin = (const float*)d_in[2];
    const float* WQ  = (const float*)d_in[3];
    const float* WK  = (const float*)d_in[4];
    const float* WV  = (const float*)d_in[5];
    const float* WO  = (const float*)d_in[6];
    const float* bQ  = (const float*)d_in[7];
    const float* bK  = (const float*)d_in[8];
    const float* bV  = (const float*)d_in[9];
    const float* bO  = (const float*)d_in[10];
    float* out = (float*)d_out;

    float *pQ, *pK, *pV, *pZ;
    cudaGetSymbolAddress((void**)&pQ, g_Q);
    cudaGetSymbolAddress((void**)&pK, g_K);
    cudaGetSymbolAddress((void**)&pV, g_V);
    cudaGetSymbolAddress((void**)&pZ, g_Z);

    const int M = Bb * Ss;       // 4096
    const int N = Hh * DHd;      // 768
    const int Kd = Dd;           // 768

    // Fused QKV projections (z selects instance)
    tgemm_k<true><<<dim3(N / 64, M / 128, 3), 256>>>(
        qin, kin, vin, WQ, WK, WV, bQ, bK, bV, pQ, pK, pV, M, N, Kd);

    int rot_threads = 2 * Bb * Ss * Hh * 32;
    rotary_k<<<rot_threads / 256, 256>>>(pQ, pK);

    size_t smem = (size_t)(64 * QP + 64 * VP + 64 * SCP) * sizeof(float);
    cudaFuncSetAttribute(attn_k, cudaFuncAttributeMaxDynamicSharedMemorySize,
                         (int)smem);
    attn_k<<<dim3(Ss / 64, Hh, Bb), 256, smem>>>(pQ, pK, pV, pZ);

    // Output projection
    tgemm_k<false><<<dim3(N / 64, M / 128, 1), 256>>>(
        pZ, pZ, pZ, WO, WO, WO, bO, bO, bO, out, out, out, M, N, Kd);
}